// round 3
// baseline (speedup 1.0000x reference)
#include <cuda_runtime.h>

// RoiAlign (TF crop_and_resize), B=8,H=64,W=64,C=256, NB=1000, P=7.
// L1tex-pipe bound: 4 LDG.128 + 1 STG.128 per float4 output (irreducible —
// corner pixels are unique per output for typical box spacing).
// R3: minimal inner loop (c4 constant per thread, p = p0+4k), max occupancy.

#define B_   8
#define H_   64
#define W_   64
#define C4_  64                    // 256 ch / 4
#define NB_  1000
#define P_   7
#define NPIX (P_ * P_)             // 49
#define ITEMS_ (NPIX * C4_)        // 3136 float4 per box

__global__ __launch_bounds__(256, 8)
void roi_align_kernel(const char* __restrict__ fm,
                      const float* __restrict__ boxes,
                      char* __restrict__ out)
{
    const int gb = blockIdx.x;           // box id 0..7999
    const int b  = gb / NB_;

    __shared__ int4   s_base[NPIX];      // 4 corner byte offsets per pixel
    __shared__ float4 s_w[NPIX];         // wx, wy, mask

    const int tid = threadIdx.x;
    if (tid < NPIX) {
        const float y1 = __ldg(&boxes[gb * 4 + 0]);
        const float x1 = __ldg(&boxes[gb * 4 + 1]);
        const float y2 = __ldg(&boxes[gb * 4 + 2]);
        const float x2 = __ldg(&boxes[gb * 4 + 3]);

        const int py = tid / P_;
        const int px = tid - py * P_;
        const float s1 = (float)(H_ - 1);   // 63

        const float ystep = (y2 - y1) * s1 / (float)(P_ - 1);
        const float xstep = (x2 - x1) * s1 / (float)(P_ - 1);
        const float yc = y1 * s1 + (float)py * ystep;
        const float xc = x1 * s1 + (float)px * xstep;

        const float ylof = floorf(yc);
        const float xlof = floorf(xc);
        const float wy = yc - ylof;
        const float wx = xc - xlof;

        const int ylo = (int)fminf(fmaxf(ylof,        0.0f), s1);
        const int yhi = (int)fminf(fmaxf(ylof + 1.0f, 0.0f), s1);
        const int xlo = (int)fminf(fmaxf(xlof,        0.0f), s1);
        const int xhi = (int)fminf(fmaxf(xlof + 1.0f, 0.0f), s1);

        const int valid = (yc >= 0.0f) & (yc <= s1) & (xc >= 0.0f) & (xc <= s1);

        const int plane = b * (H_ * W_);
        const int rlo = (plane + ylo * W_);
        const int rhi = (plane + yhi * W_);
        s_base[tid] = make_int4((rlo + xlo) << 10, (rlo + xhi) << 10,
                                (rhi + xlo) << 10, (rhi + xhi) << 10);
        s_w[tid] = make_float4(wx, wy, valid ? 1.0f : 0.0f, 0.0f);
    }
    __syncthreads();

    // Per-thread invariants: channel byte offset is constant across k
    // (256 is a multiple of 64); pixel index advances by 4 each k.
    const int c4b = (tid & (C4_ - 1)) << 4;
    int p = tid >> 6;                            // 0..3
    const char* fmc = fm + c4b;
    char* o = out + (long long)gb * (ITEMS_ * 16) + ((long long)tid << 4);

    #pragma unroll 1
    for (int k = 0; k < 12; k++, p += 4, o += 256 * 16) {
        const int4   bb = s_base[p];
        const float4 wv = s_w[p];

        const float4 v00 = __ldg((const float4*)(fmc + bb.x));
        const float4 v01 = __ldg((const float4*)(fmc + bb.y));
        const float4 v10 = __ldg((const float4*)(fmc + bb.z));
        const float4 v11 = __ldg((const float4*)(fmc + bb.w));

        float4 r;
        float tx, bx;
        tx = fmaf(v01.x - v00.x, wv.x, v00.x);
        bx = fmaf(v11.x - v10.x, wv.x, v10.x);
        r.x = fmaf(bx - tx, wv.y, tx) * wv.z;
        tx = fmaf(v01.y - v00.y, wv.x, v00.y);
        bx = fmaf(v11.y - v10.y, wv.x, v10.y);
        r.y = fmaf(bx - tx, wv.y, tx) * wv.z;
        tx = fmaf(v01.z - v00.z, wv.x, v00.z);
        bx = fmaf(v11.z - v10.z, wv.x, v10.z);
        r.z = fmaf(bx - tx, wv.y, tx) * wv.z;
        tx = fmaf(v01.w - v00.w, wv.x, v00.w);
        bx = fmaf(v11.w - v10.w, wv.x, v10.w);
        r.w = fmaf(bx - tx, wv.y, tx) * wv.z;

        __stcs((float4*)o, r);
    }

    // tail: p0 + 48 valid only for tid < 64 (pixel 48)
    if (p < NPIX) {
        const int4   bb = s_base[p];
        const float4 wv = s_w[p];

        const float4 v00 = __ldg((const float4*)(fmc + bb.x));
        const float4 v01 = __ldg((const float4*)(fmc + bb.y));
        const float4 v10 = __ldg((const float4*)(fmc + bb.z));
        const float4 v11 = __ldg((const float4*)(fmc + bb.w));

        float4 r;
        float tx, bx;
        tx = fmaf(v01.x - v00.x, wv.x, v00.x);
        bx = fmaf(v11.x - v10.x, wv.x, v10.x);
        r.x = fmaf(bx - tx, wv.y, tx) * wv.z;
        tx = fmaf(v01.y - v00.y, wv.x, v00.y);
        bx = fmaf(v11.y - v10.y, wv.x, v10.y);
        r.y = fmaf(bx - tx, wv.y, tx) * wv.z;
        tx = fmaf(v01.z - v00.z, wv.x, v00.z);
        bx = fmaf(v11.z - v10.z, wv.x, v10.z);
        r.z = fmaf(bx - tx, wv.y, tx) * wv.z;
        tx = fmaf(v01.w - v00.w, wv.x, v00.w);
        bx = fmaf(v11.w - v10.w, wv.x, v10.w);
        r.w = fmaf(bx - tx, wv.y, tx) * wv.z;

        __stcs((float4*)o, r);
    }
}

extern "C" void kernel_launch(void* const* d_in, const int* in_sizes, int n_in,
                              void* d_out, int out_size)
{
    const char*  fm    = (const char*)d_in[0];
    const float* boxes = (const float*)d_in[1];
    char*        out   = (char*)d_out;

    roi_align_kernel<<<B_ * NB_, 256>>>(fm, boxes, out);
}